// round 12
// baseline (speedup 1.0000x reference)
#include <cuda_runtime.h>
#include <math.h>

#define POOLED   7
#define CHANNELS 256
#define BATCH    4
#define H        50
#define W        50
#define HW       (H*W)
#define SCALE    0.0625f

#define CG        4                 // channels per block
#define ROI_SPLIT 2                 // roi halves
#define RPB       (128 / ROI_SPLIT) // rois per block (candidates)
#define NTHREADS  224               // 7 warps; 196 compute threads (4*49)
#define PAD       2501              // 2501 mod 32 = 5 -> conflict-light

// Fused RoIPool: stage CG feature planes in smem, compute all (roi,bin) maxes.
__global__ void __launch_bounds__(NTHREADS)
roipool_fused(const float* __restrict__ feat,
              const float* __restrict__ rois,
              float* __restrict__ out)
{
    __shared__ float sfeat[CG][PAD];     // 4 x 2501 floats = 40016 B
    __shared__ float srois[RPB * 5];     // this half's rois (320 floats)

    int cg  = blockIdx.x;                // 0..63
    int b   = blockIdx.y;                // 0..3
    int z   = blockIdx.z;                // 0..ROI_SPLIT-1
    int tid = threadIdx.x;

    // ---- Load 4 feature planes, coalesced float4 from NCHW ----
    // planes for channels cg*4 .. cg*4+3 are contiguous: 2500 float4 total
    const float4* src4 = (const float4*)(feat + ((size_t)b * CHANNELS + cg * CG) * HW);
    for (int k = tid; k < CG * (HW / 4); k += NTHREADS) {
        int ci = k / (HW / 4);
        int j  = k - ci * (HW / 4);
        float4 v = src4[k];
        float* d = &sfeat[ci][j * 4];
        d[0] = v.x; d[1] = v.y; d[2] = v.z; d[3] = v.w;
    }
    // ---- Load this half's rois (grid-stride: 320 > NTHREADS) ----
    for (int k = tid; k < RPB * 5; k += NTHREADS)
        srois[k] = rois[z * RPB * 5 + k];
    __syncthreads();

    if (tid >= CG * 49) return;

    int c_local = tid / 49;
    int bin     = tid - c_local * 49;
    int ph      = bin / POOLED;
    int pw      = bin - ph * POOLED;
    float pwf   = (float)pw;
    float phf   = (float)ph;

    const float* sp = &sfeat[c_local][0];
    float* outc = out + (size_t)(cg * CG + c_local) * 49 + bin;
    const float inv7 = 1.0f / 7.0f;   // match XLA-CPU fast-math x*(1/7)

    for (int rl = 0; rl < RPB; ++rl) {
        const float* roi = &srois[rl * 5];
        if ((int)roi[0] != b) continue;          // uniform across block
        int r = z * RPB + rl;

        float x1 = floorf(__fadd_rn(__fmul_rn(roi[1], SCALE), 0.5f));
        float y1 = floorf(__fadd_rn(__fmul_rn(roi[2], SCALE), 0.5f));
        float x2 = floorf(__fadd_rn(__fmul_rn(roi[3], SCALE), 0.5f));
        float y2 = floorf(__fadd_rn(__fmul_rn(roi[4], SCALE), 0.5f));

        float roi_w = fmaxf(__fadd_rn(__fadd_rn(x2, -x1), 1.0f), 1.0f);
        float roi_h = fmaxf(__fadd_rn(__fadd_rn(y2, -y1), 1.0f), 1.0f);
        float bin_w = __fmul_rn(roi_w, inv7);
        float bin_h = __fmul_rn(roi_h, inv7);

        float ws = fminf(fmaxf(__fadd_rn(floorf(__fmul_rn(pwf, bin_w)), x1), 0.0f), (float)W);
        float we = fminf(fmaxf(__fadd_rn(ceilf(__fmul_rn(__fadd_rn(pwf, 1.0f), bin_w)), x1), 0.0f), (float)W);
        float hs = fminf(fmaxf(__fadd_rn(floorf(__fmul_rn(phf, bin_h)), y1), 0.0f), (float)H);
        float he = fminf(fmaxf(__fadd_rn(ceilf(__fmul_rn(__fadd_rn(phf, 1.0f), bin_h)), y1), 0.0f), (float)H);

        int iws = (int)ws, iwe = (int)we;
        int ihs = (int)hs, ihe = (int)he;

        float m;
        if (ihe <= ihs || iwe <= iws) {
            m = 0.0f;
        } else {
            m = -INFINITY;
            for (int h = ihs; h < ihe; ++h) {
                const float* rowp = sp + h * W;
                for (int w = iws; w < iwe; ++w)
                    m = fmaxf(m, rowp[w]);
            }
        }
        outc[(size_t)r * 12544] = m;   // out[r][c][bin]
    }
}

extern "C" void kernel_launch(void* const* d_in, const int* in_sizes, int n_in,
                              void* d_out, int out_size)
{
    const float* feat = (const float*)d_in[0];
    const float* rois = (const float*)d_in[1];
    float* out = (float*)d_out;

    dim3 grid(CHANNELS / CG, BATCH, ROI_SPLIT);   // 64 x 4 x 2 = 512 blocks
    roipool_fused<<<grid, NTHREADS>>>(feat, rois, out);
}

// round 13
// speedup vs baseline: 1.5524x; 1.5524x over previous
#include <cuda_runtime.h>
#include <math.h>

#define POOLED   7
#define CHANNELS 256
#define BATCH    4
#define H        50
#define W        50
#define HW       (H*W)
#define SCALE    0.0625f

// NHWC scratch: featT[b][h][w][c]
__device__ float g_featT[(size_t)BATCH * HW * CHANNELS];
// Pool output scratch: g_outT[r][bin][c]  (128 * 49 * 256 f32 = 6.4 MB)
__device__ float g_outT[(size_t)128 * 49 * CHANNELS];

// ------- Transpose NCHW -> NHWC, batched loads (MLP=4), float4 both ways ----
__global__ void __launch_bounds__(256)
transpose_kernel(const float* __restrict__ feat)
{
    __shared__ float4 tile[32 * 33];   // [c][hw4], pad 33 -> conflict-free

    int b    = blockIdx.z;
    int hw0  = blockIdx.x * 128;
    int c0   = blockIdx.y * 32;
    int lane = threadIdx.x & 31;
    int wid  = threadIdx.x >> 5;       // 0..7

    const float* in = feat + (size_t)b * CHANNELS * HW;
    bool hv = (hw0 + lane * 4) < HW;   // hw tail: 68 = 17 float4 exactly

    // 4 independent LDG.128 issued back-to-back, THEN stores.
    float4 v[4];
    #pragma unroll
    for (int i = 0; i < 4; ++i) {
        int c = c0 + wid + i * 8;
        const float4* src = (const float4*)(in + (size_t)c * HW + hw0) + lane;
        if (hv) v[i] = *src;
    }
    #pragma unroll
    for (int i = 0; i < 4; ++i)
        if (hv) tile[(wid + i * 8) * 33 + lane] = v[i];
    __syncthreads();

    // Batched LDS.128, then 16 coalesced STG.32.
    float* outp = g_featT + (size_t)b * HW * CHANNELS + c0;
    float4 u[4];
    #pragma unroll
    for (int j = 0; j < 4; ++j)
        u[j] = tile[lane * 33 + (wid + j * 8)];
    #pragma unroll
    for (int j = 0; j < 4; ++j) {
        int hw = hw0 + (wid + j * 8) * 4;
        if (hw < HW) {
            outp[(size_t)(hw + 0) * CHANNELS + lane] = u[j].x;
            outp[(size_t)(hw + 1) * CHANNELS + lane] = u[j].y;
            outp[(size_t)(hw + 2) * CHANNELS + lane] = u[j].z;
            outp[(size_t)(hw + 3) * CHANNELS + lane] = u[j].w;
        }
    }
}

// ------------- RoI max-pool: block = (roi, bin), coalesced stores -----------
__global__ void __launch_bounds__(128)
roipool_kernel6(const float* __restrict__ rois)
{
    __shared__ int soff[96];       // padded pixel offsets (float2 units), max 88

    int blk = blockIdx.x;          // r*49 + bin
    int r   = blk / 49;
    int bin = blk - r * 49;
    int ph  = bin / POOLED;
    int pw  = bin - ph * POOLED;
    int t   = threadIdx.x;         // 0..127 -> channels 2t, 2t+1

    const float* roi = rois + r * 5;
    int   b  = (int)roi[0];
    float x1 = floorf(__fadd_rn(__fmul_rn(roi[1], SCALE), 0.5f));
    float y1 = floorf(__fadd_rn(__fmul_rn(roi[2], SCALE), 0.5f));
    float x2 = floorf(__fadd_rn(__fmul_rn(roi[3], SCALE), 0.5f));
    float y2 = floorf(__fadd_rn(__fmul_rn(roi[4], SCALE), 0.5f));

    float roi_w = fmaxf(__fadd_rn(__fadd_rn(x2, -x1), 1.0f), 1.0f);
    float roi_h = fmaxf(__fadd_rn(__fadd_rn(y2, -y1), 1.0f), 1.0f);

    // Match XLA-CPU fast-math: x/7 lowered to x * fl32(1/7)
    const float inv7 = 1.0f / 7.0f;
    float bin_w = __fmul_rn(roi_w, inv7);
    float bin_h = __fmul_rn(roi_h, inv7);

    float pwf = (float)pw;
    float phf = (float)ph;

    float ws = fminf(fmaxf(__fadd_rn(floorf(__fmul_rn(pwf, bin_w)), x1), 0.0f), (float)W);
    float we = fminf(fmaxf(__fadd_rn(ceilf(__fmul_rn(__fadd_rn(pwf, 1.0f), bin_w)), x1), 0.0f), (float)W);
    float hs = fminf(fmaxf(__fadd_rn(floorf(__fmul_rn(phf, bin_h)), y1), 0.0f), (float)H);
    float he = fminf(fmaxf(__fadd_rn(ceilf(__fmul_rn(__fadd_rn(phf, 1.0f), bin_h)), y1), 0.0f), (float)H);

    int iws = (int)ws, iwe = (int)we;
    int ihs = (int)hs, ihe = (int)he;

    // Coalesced store target: g_outT[blk][c], c = 2t, 2t+1 -> one STG.64
    float2* o2 = (float2*)(g_outT + (size_t)blk * CHANNELS) + t;

    if (ihe <= ihs || iwe <= iws) {     // block-uniform
        *o2 = make_float2(0.0f, 0.0f);
        return;
    }

    int bw    = iwe - iws;                      // <= 9 after clamping
    int n     = (ihe - ihs) * bw;               // <= 81
    int n_pad = (n + 7) & ~7;                   // <= 88 < 96 (MLP-8 groups)

    // Build offset table: one int div per participating thread, once.
    if (t < n_pad) {
        int p = min(t, n - 1);                  // pad by replicating last pixel
        int h = p / bw;
        int w = p - h * bw;
        soff[t] = ((ihs + h) * W + (iws + w)) * 128;   // float2 units
    }
    __syncthreads();

    const float2* base = (const float2*)(g_featT + (size_t)b * HW * CHANNELS) + t;

    float2 m = make_float2(-INFINITY, -INFINITY);
    for (int p = 0; p < n_pad; p += 8) {
        int4 oa = *(const int4*)&soff[p];       // LDS.128, warp-broadcast
        int4 ob = *(const int4*)&soff[p + 4];
        // 8 independent LDG.64 in flight before any consume
        float2 v0 = __ldg(base + oa.x);
        float2 v1 = __ldg(base + oa.y);
        float2 v2 = __ldg(base + oa.z);
        float2 v3 = __ldg(base + oa.w);
        float2 v4 = __ldg(base + ob.x);
        float2 v5 = __ldg(base + ob.y);
        float2 v6 = __ldg(base + ob.z);
        float2 v7 = __ldg(base + ob.w);
        float ax = fmaxf(fmaxf(v0.x, v1.x), fmaxf(v2.x, v3.x));
        float bx = fmaxf(fmaxf(v4.x, v5.x), fmaxf(v6.x, v7.x));
        float ay = fmaxf(fmaxf(v0.y, v1.y), fmaxf(v2.y, v3.y));
        float by = fmaxf(fmaxf(v4.y, v5.y), fmaxf(v6.y, v7.y));
        m.x = fmaxf(m.x, fmaxf(ax, bx));
        m.y = fmaxf(m.y, fmaxf(ay, by));
    }

    *o2 = m;
}

// ------------- Output transpose: g_outT[r][bin][c] -> out[r][c][bin] --------
__global__ void __launch_bounds__(256)
out_transpose_kernel(float* __restrict__ out)
{
    __shared__ float tile[32][33];

    int r    = blockIdx.z;
    int bin0 = blockIdx.x * 32;     // 0 or 32
    int c0   = blockIdx.y * 32;
    int tx   = threadIdx.x;         // 0..31
    int ty   = threadIdx.y;         // 0..7

    const float* in = g_outT + (size_t)r * 49 * CHANNELS;

    // Batched loads (4 independent LDG), then stores.
    float v[4];
    #pragma unroll
    for (int i = 0; i < 4; ++i) {
        int bin = bin0 + ty + i * 8;
        if (bin < 49)
            v[i] = in[(size_t)bin * CHANNELS + c0 + tx];
    }
    #pragma unroll
    for (int i = 0; i < 4; ++i) {
        int bin = bin0 + ty + i * 8;
        if (bin < 49)
            tile[ty + i * 8][tx] = v[i];
    }
    __syncthreads();

    float* op = out + (size_t)r * 12544;
    float u[4];
    #pragma unroll
    for (int i = 0; i < 4; ++i)
        u[i] = tile[tx][ty + i * 8];
    #pragma unroll
    for (int i = 0; i < 4; ++i) {
        int c   = c0 + ty + i * 8;
        int bin = bin0 + tx;
        if (bin < 49)
            op[(size_t)c * 49 + bin] = u[i];
    }
}

extern "C" void kernel_launch(void* const* d_in, const int* in_sizes, int n_in,
                              void* d_out, int out_size)
{
    const float* feat = (const float*)d_in[0];
    const float* rois = (const float*)d_in[1];
    float* out = (float*)d_out;

    dim3 tgrid((HW + 127) / 128, CHANNELS / 32, BATCH);   // 20 x 8 x 4
    transpose_kernel<<<tgrid, 256>>>(feat);

    int blocks = 128 * 49;   // (roi, bin) = 6272
    roipool_kernel6<<<blocks, 128>>>(rois);

    dim3 ogrid(2, CHANNELS / 32, 128);   // 2 x 8 x 128
    dim3 oblk(32, 8);
    out_transpose_kernel<<<ogrid, oblk>>>(out);
}